// round 8
// baseline (speedup 1.0000x reference)
#include <cuda_runtime.h>
#include <cuda_bf16.h>
#include <stdint.h>
#include <math.h>

#define Cc   512
#define Gg   32
#define CPG  16
#define Nn   4096
#define Bb   2
#define EPSf 1e-6f
#define SCALEf 0.04419417382415922f   // 512^-0.5

// ---------------- device scratch (static; no runtime alloc) ----------------
__device__ __nv_bfloat16 g_ht[(size_t)Bb * Nn * Cc];   // h  [b][n][c]
__device__ __nv_bfloat16 g_qt[(size_t)Bb * Nn * Cc];   // q  [b][n][d] (pre-scaled)
__device__ __nv_bfloat16 g_kt[(size_t)Bb * Nn * Cc];   // k  [b][n][d]
__device__ __nv_bfloat16 g_vv[(size_t)Bb * Cc * Nn];   // v  [b][c][n]
__device__ __nv_bfloat16 g_ot[(size_t)Bb * Nn * Cc];   // o  [b][n][c]
__device__ __nv_bfloat16 g_s [(size_t)Bb * Nn * Nn];   // scores / probs [b][i][j]
__device__ __nv_bfloat16 g_wq[Cc * Cc], g_wk[Cc * Cc], g_wv[Cc * Cc], g_wp[Cc * Cc];
__device__ float g_stats[Bb * Gg * 2];

// ---------------- helpers ----------------------------------------------------
__device__ __forceinline__ uint32_t s2u(const void* p) {
    return (uint32_t)__cvta_generic_to_shared((void*)p);
}
__device__ __forceinline__ void cp16(uint32_t saddr, const void* gaddr) {
    asm volatile("cp.async.cg.shared.global [%0], [%1], 16;" :: "r"(saddr), "l"(gaddr));
}
__device__ __forceinline__ void cp_commit() {
    asm volatile("cp.async.commit_group;" ::: "memory");
}
template <int N>
__device__ __forceinline__ void cp_wait() {
    asm volatile("cp.async.wait_group %0;" :: "n"(N) : "memory");
}
__device__ __forceinline__ void ldm4(uint32_t& r0, uint32_t& r1, uint32_t& r2, uint32_t& r3,
                                     uint32_t addr) {
    asm volatile("ldmatrix.sync.aligned.m8n8.x4.shared.b16 {%0,%1,%2,%3}, [%4];"
                 : "=r"(r0), "=r"(r1), "=r"(r2), "=r"(r3) : "r"(addr));
}
__device__ __forceinline__ void mma16816(float* d, const uint32_t* a, const uint32_t* b) {
    asm volatile("mma.sync.aligned.m16n8k16.row.col.f32.bf16.bf16.f32 "
                 "{%0,%1,%2,%3}, {%4,%5,%6,%7}, {%8,%9}, {%0,%1,%2,%3};"
                 : "+f"(d[0]), "+f"(d[1]), "+f"(d[2]), "+f"(d[3])
                 : "r"(a[0]), "r"(a[1]), "r"(a[2]), "r"(a[3]), "r"(b[0]), "r"(b[1]));
}
// SW128 swizzle for 128B rows: element (row, 16B-chunk c in 0..7)
__device__ __forceinline__ uint32_t smoff(int row, int c) {
    return (uint32_t)(row * 128 + ((c ^ (row & 7)) << 4));
}
__device__ __forceinline__ float fexp(float x) {
    x = fmaxf(x, -87.f);
    float z  = x * 1.4426950408889634f;
    float zi = rintf(z);
    float zf = z - zi;
    float r = 1.33978439e-3f;
    r = fmaf(r, zf, 9.67580429e-3f);
    r = fmaf(r, zf, 5.55041087e-2f);
    r = fmaf(r, zf, 2.40226507e-1f);
    r = fmaf(r, zf, 6.93147182e-1f);
    r = fmaf(r, zf, 1.0f);
    return r * __int_as_float(((int)zi + 127) << 23);
}

// ---------------- weight fp32 -> bf16 ---------------------------------------
__global__ void conv_w_kernel(const float* __restrict__ a, const float* __restrict__ b,
                              const float* __restrict__ c, const float* __restrict__ d,
                              __nv_bfloat16* oa, __nv_bfloat16* ob,
                              __nv_bfloat16* oc, __nv_bfloat16* od) {
    int i = blockIdx.x * blockDim.x + threadIdx.x;
    const float4* src[4] = {(const float4*)a, (const float4*)b, (const float4*)c, (const float4*)d};
    __nv_bfloat162* dst[4] = {(__nv_bfloat162*)oa, (__nv_bfloat162*)ob,
                              (__nv_bfloat162*)oc, (__nv_bfloat162*)od};
    #pragma unroll
    for (int m = 0; m < 4; m++) {
        float4 v = src[m][i];
        dst[m][i * 2 + 0] = __nv_bfloat162(__float2bfloat16(v.x), __float2bfloat16(v.y));
        dst[m][i * 2 + 1] = __nv_bfloat162(__float2bfloat16(v.z), __float2bfloat16(v.w));
    }
}

// ---------------- GroupNorm stats -------------------------------------------
__global__ void gn_stats_kernel(const float* __restrict__ x, float* __restrict__ stats) {
    const int bg = blockIdx.x;
    const size_t base = (size_t)bg * CPG * Nn;
    const int n_el = CPG * Nn;
    float s = 0.f, ss = 0.f;
    for (int i = threadIdx.x; i < n_el; i += blockDim.x) {
        float v = x[base + i];
        s += v; ss += v * v;
    }
    __shared__ float red[16];
    #pragma unroll
    for (int o = 16; o; o >>= 1) {
        s  += __shfl_down_sync(0xffffffffu, s,  o);
        ss += __shfl_down_sync(0xffffffffu, ss, o);
    }
    const int wid = threadIdx.x >> 5, lane = threadIdx.x & 31;
    if (lane == 0) { red[wid] = s; red[8 + wid] = ss; }
    __syncthreads();
    if (threadIdx.x == 0) {
        float ts = 0.f, tss = 0.f;
        #pragma unroll
        for (int i = 0; i < 8; i++) { ts += red[i]; tss += red[8 + i]; }
        float mu = ts / (float)n_el;
        float var = tss / (float)n_el - mu * mu;
        stats[bg * 2 + 0] = mu;
        stats[bg * 2 + 1] = rsqrtf(var + EPSf);
    }
}

// ---------------- normalize + transpose x[b][c][n] -> h[b][n][c] bf16 -------
__global__ void gn_norm_t_kernel(const float* __restrict__ x,
                                 const float* __restrict__ w, const float* __restrict__ b,
                                 const float* __restrict__ stats,
                                 __nv_bfloat16* __restrict__ ht) {
    __shared__ float tile[64][65];
    const int n0 = blockIdx.x * 64, c0 = blockIdx.y * 64, bz = blockIdx.z;
    const int tid = threadIdx.x;
    const float* xb = x + (size_t)bz * Cc * Nn;
    #pragma unroll
    for (int i = 0; i < 4; i++) {
        int vi = tid + i * 256;
        int r = vi >> 4, seg = (vi & 15) * 4;
        float4 v = *(const float4*)&xb[(size_t)(c0 + r) * Nn + n0 + seg];
        tile[r][seg + 0] = v.x; tile[r][seg + 1] = v.y;
        tile[r][seg + 2] = v.z; tile[r][seg + 3] = v.w;
    }
    __syncthreads();
    const int nr = tid >> 2, cs = (tid & 3) * 16;
    __nv_bfloat16* hrow = ht + ((size_t)bz * Nn + n0 + nr) * Cc + c0;
    #pragma unroll
    for (int c = 0; c < 16; c++) {
        int cg = cs + c, ch = c0 + cg;
        int sidx = (bz * Gg + (ch >> 4)) * 2;
        float mu = stats[sidx], inv = stats[sidx + 1];
        hrow[cg] = __float2bfloat16((tile[cg][nr] - mu) * inv * w[ch] + b[ch]);
    }
}

// ---------------- bf16 HMMA GEMM: C[M][N] = A[M][K] @ B[N][K]^T --------------
// Tile 128(M) x 256(N) x 64(K), 256 threads (8 warps, 2x4), warp tile 64x64.
// 4-stage cp.async pipeline (192 KB SMEM), one barrier per 64-wide k-tile.
enum { MQ = 0, MK = 1, MV = 2, MS = 3, MA = 4, MP = 5 };
#define BKg 64
#define STAGES 4
#define A_BYTES 16384                  // 128 x 64 bf16
#define B_BYTES 32768                  // 256 x 64 bf16
#define STG_BYTES (A_BYTES + B_BYTES)  // 48 KB
#define GEMM_SMEM (STAGES * STG_BYTES) // 192 KB

template <int MODE>
__global__ __launch_bounds__(256, 1)
void hgemm(const __nv_bfloat16* __restrict__ A, const __nv_bfloat16* __restrict__ B,
           void* __restrict__ OutP, int lda, int ldb, int Nd, int K,
           const float* __restrict__ bias, const float* __restrict__ resid,
           long long sA, long long sB, long long sO, long long sR) {
    extern __shared__ char smem[];
    const uint32_t sbase = s2u(smem);
    const int tid = threadIdx.x, lane = tid & 31, warp = tid >> 5;
    const int wmB = (warp >> 2) * 64, wnB = (warp & 3) * 64;   // 2x4 warp grid
    const int m0 = blockIdx.y * 128, n0 = blockIdx.x * 256;
    const int bz = blockIdx.z;

    const __nv_bfloat16* gA = A + (size_t)bz * sA + (size_t)m0 * lda;
    const __nv_bfloat16* gB = B + (size_t)bz * sB + (size_t)n0 * ldb;

    // cp.async coords: rows of 128B = 8 chunks; thread covers (tid>>3 + 32*i, tid&7)
    const int rr = tid >> 3, cch = tid & 7;
    uint32_t sofA[4], sofB[8];
    size_t gofA[4], gofB[8];
    #pragma unroll
    for (int i = 0; i < 4; i++) {
        sofA[i] = smoff(rr + 32 * i, cch);
        gofA[i] = (size_t)(rr + 32 * i) * lda + cch * 8;
    }
    #pragma unroll
    for (int i = 0; i < 8; i++) {
        sofB[i] = smoff(rr + 32 * i, cch);
        gofB[i] = (size_t)(rr + 32 * i) * ldb + cch * 8;
    }

    const int NT = K / BKg;
    // ---- prologue: prefetch stages 0..STAGES-2
    #pragma unroll
    for (int t = 0; t < STAGES - 1; t++) {
        if (t < NT) {
            const __nv_bfloat16* a_src = gA + t * BKg;
            const __nv_bfloat16* b_src = gB + t * BKg;
            uint32_t sa = sbase + t * STG_BYTES;
            #pragma unroll
            for (int i = 0; i < 4; i++) cp16(sa + sofA[i], a_src + gofA[i]);
            #pragma unroll
            for (int i = 0; i < 8; i++) cp16(sa + A_BYTES + sofB[i], b_src + gofB[i]);
        }
        cp_commit();
    }

    float acc[4][8][4];
    #pragma unroll
    for (int i = 0; i < 4; i++)
        #pragma unroll
        for (int j = 0; j < 8; j++)
            #pragma unroll
            for (int k = 0; k < 4; k++) acc[i][j][k] = 0.f;

    const int aRow = lane & 15, aC = lane >> 4;
    const int bRow = (lane & 7) + ((lane & 16) >> 1), bC = (lane >> 3) & 1;

    for (int t = 0; t < NT; t++) {
        if (t >= NT - (STAGES - 1)) cp_wait<0>(); else cp_wait<STAGES - 2>();
        __syncthreads();     // stage t ready; all warps done reading the slot
                             // that iteration t's prefetch will overwrite
        if (t + STAGES - 1 < NT) {
            int tp = t + STAGES - 1;
            const __nv_bfloat16* a_src = gA + tp * BKg;
            const __nv_bfloat16* b_src = gB + tp * BKg;
            uint32_t sa = sbase + (tp % STAGES) * STG_BYTES;
            #pragma unroll
            for (int i = 0; i < 4; i++) cp16(sa + sofA[i], a_src + gofA[i]);
            #pragma unroll
            for (int i = 0; i < 8; i++) cp16(sa + A_BYTES + sofB[i], b_src + gofB[i]);
        }
        cp_commit();
        const uint32_t aS = sbase + (t % STAGES) * STG_BYTES;
        const uint32_t bS = aS + A_BYTES;
        #pragma unroll
        for (int kk = 0; kk < 4; kk++) {
            uint32_t af[4][4], bf[8][2];
            #pragma unroll
            for (int mf = 0; mf < 4; mf++)
                ldm4(af[mf][0], af[mf][1], af[mf][2], af[mf][3],
                     aS + smoff(wmB + mf * 16 + aRow, kk * 2 + aC));
            #pragma unroll
            for (int g = 0; g < 4; g++)
                ldm4(bf[2 * g][0], bf[2 * g][1], bf[2 * g + 1][0], bf[2 * g + 1][1],
                     bS + smoff(wnB + g * 16 + bRow, kk * 2 + bC));
            #pragma unroll
            for (int mf = 0; mf < 4; mf++)
                #pragma unroll
                for (int nf = 0; nf < 8; nf++)
                    mma16816(acc[mf][nf], af[mf], bf[nf]);
        }
    }

    // ---- epilogue
    float* Of = (float*)OutP + (size_t)bz * sO;
    __nv_bfloat16* Oh = (__nv_bfloat16*)OutP + (size_t)bz * sO;
    const float* Rz = resid + (size_t)bz * sR;
    #pragma unroll
    for (int mf = 0; mf < 4; mf++) {
        #pragma unroll
        for (int pr = 0; pr < 2; pr++) {
            const int row = m0 + wmB + mf * 16 + (lane >> 2) + pr * 8;
            float rb = 0.f;
            if (MODE == MV || MODE == MP) rb = bias[row];
            #pragma unroll
            for (int nf = 0; nf < 8; nf++) {
                const int col = n0 + wnB + nf * 8 + (lane & 3) * 2;
                float v0 = acc[mf][nf][pr * 2 + 0];
                float v1 = acc[mf][nf][pr * 2 + 1];
                if (MODE == MQ) { v0 = (v0 + bias[col]) * SCALEf; v1 = (v1 + bias[col + 1]) * SCALEf; }
                if (MODE == MK) { v0 += bias[col]; v1 += bias[col + 1]; }
                if (MODE == MV || MODE == MP) { v0 += rb; v1 += rb; }
                const size_t oi = (size_t)row * Nd + col;
                if (MODE == MP) {
                    float2 rrv = *(const float2*)&Rz[oi];
                    *(float2*)&Of[oi] = make_float2(v0 + rrv.x, v1 + rrv.y);
                } else {
                    *(__nv_bfloat162*)&Oh[oi] =
                        __nv_bfloat162(__float2bfloat16(v0), __float2bfloat16(v1));
                }
            }
        }
    }
}

// ---------------- row softmax (in-place, bf16 rows of 4096) -----------------
__global__ void softmax_row_kernel(__nv_bfloat16* __restrict__ s) {
    __nv_bfloat16* p = s + (size_t)blockIdx.x * Nn;
    const int tid = threadIdx.x;
    float v[16];
    uint4 raw[2];
    #pragma unroll
    for (int h = 0; h < 2; h++) {
        raw[h] = *(const uint4*)(p + (tid + h * 256) * 8);
        const __nv_bfloat16* pb = (const __nv_bfloat16*)&raw[h];
        #pragma unroll
        for (int e = 0; e < 8; e++) v[h * 8 + e] = __bfloat162float(pb[e]);
    }
    float mx = -1e30f;
    #pragma unroll
    for (int i = 0; i < 16; i++) mx = fmaxf(mx, v[i]);
    __shared__ float red[8];
    const int wid = tid >> 5, lane = tid & 31;
    #pragma unroll
    for (int o = 16; o; o >>= 1) mx = fmaxf(mx, __shfl_xor_sync(0xffffffffu, mx, o));
    if (lane == 0) red[wid] = mx;
    __syncthreads();
    mx = red[0];
    #pragma unroll
    for (int i = 1; i < 8; i++) mx = fmaxf(mx, red[i]);
    __syncthreads();
    float sum = 0.f;
    #pragma unroll
    for (int i = 0; i < 16; i++) { v[i] = fexp(v[i] - mx); sum += v[i]; }
    #pragma unroll
    for (int o = 16; o; o >>= 1) sum += __shfl_xor_sync(0xffffffffu, sum, o);
    if (lane == 0) red[wid] = sum;
    __syncthreads();
    sum = 0.f;
    #pragma unroll
    for (int i = 0; i < 8; i++) sum += red[i];
    const float inv = 1.f / sum;
    #pragma unroll
    for (int h = 0; h < 2; h++) {
        uint4 outp;
        __nv_bfloat16* ob = (__nv_bfloat16*)&outp;
        #pragma unroll
        for (int e = 0; e < 8; e++) ob[e] = __float2bfloat16(v[h * 8 + e] * inv);
        *(uint4*)(p + (tid + h * 256) * 8) = outp;
    }
}

// ---------------- launch -----------------------------------------------------
extern "C" void kernel_launch(void* const* d_in, const int* in_sizes, int n_in,
                              void* d_out, int out_size) {
    const float* x  = (const float*)d_in[0];
    const float* gw = (const float*)d_in[1];
    const float* gb = (const float*)d_in[2];
    const float* wq = (const float*)d_in[3];
    const float* bq = (const float*)d_in[4];
    const float* wk = (const float*)d_in[5];
    const float* bk = (const float*)d_in[6];
    const float* wv = (const float*)d_in[7];
    const float* bv = (const float*)d_in[8];
    const float* wp = (const float*)d_in[9];
    const float* bp = (const float*)d_in[10];
    float* out = (float*)d_out;

    __nv_bfloat16 *ht, *qt, *kt, *vv, *ot, *sc, *bwq, *bwk, *bwv, *bwp;
    float* stats;
    cudaGetSymbolAddress((void**)&ht, g_ht);
    cudaGetSymbolAddress((void**)&qt, g_qt);
    cudaGetSymbolAddress((void**)&kt, g_kt);
    cudaGetSymbolAddress((void**)&vv, g_vv);
    cudaGetSymbolAddress((void**)&ot, g_ot);
    cudaGetSymbolAddress((void**)&sc, g_s);
    cudaGetSymbolAddress((void**)&bwq, g_wq);
    cudaGetSymbolAddress((void**)&bwk, g_wk);
    cudaGetSymbolAddress((void**)&bwv, g_wv);
    cudaGetSymbolAddress((void**)&bwp, g_wp);
    cudaGetSymbolAddress((void**)&stats, g_stats);

    cudaFuncSetAttribute(hgemm<MQ>, cudaFuncAttributeMaxDynamicSharedMemorySize, GEMM_SMEM);
    cudaFuncSetAttribute(hgemm<MK>, cudaFuncAttributeMaxDynamicSharedMemorySize, GEMM_SMEM);
    cudaFuncSetAttribute(hgemm<MV>, cudaFuncAttributeMaxDynamicSharedMemorySize, GEMM_SMEM);
    cudaFuncSetAttribute(hgemm<MS>, cudaFuncAttributeMaxDynamicSharedMemorySize, GEMM_SMEM);
    cudaFuncSetAttribute(hgemm<MA>, cudaFuncAttributeMaxDynamicSharedMemorySize, GEMM_SMEM);
    cudaFuncSetAttribute(hgemm<MP>, cudaFuncAttributeMaxDynamicSharedMemorySize, GEMM_SMEM);

    const long long NC_ = (long long)Nn * Cc;
    const long long CN_ = (long long)Cc * Nn;
    const long long NN_ = (long long)Nn * Nn;

    conv_w_kernel<<<256, 256>>>(wq, wk, wv, wp, bwq, bwk, bwv, bwp);
    gn_stats_kernel<<<Bb * Gg, 256>>>(x, stats);
    gn_norm_t_kernel<<<dim3(Nn / 64, Cc / 64, Bb), 256>>>(x, gw, gb, stats, ht);

    // q[n][d] = scale*(h[n][:] @ Wq[d][:] + bq)    M=4096 N=512 K=512
    hgemm<MQ><<<dim3(2, 32, Bb), 256, GEMM_SMEM>>>(ht, bwq, qt, Cc, Cc, Cc, Cc,
                                                   bq, nullptr, NC_, 0, NC_, 0);
    hgemm<MK><<<dim3(2, 32, Bb), 256, GEMM_SMEM>>>(ht, bwk, kt, Cc, Cc, Cc, Cc,
                                                   bk, nullptr, NC_, 0, NC_, 0);
    // v[c][n] = Wv[c][:] @ h[n][:] + bv[c]         M=512 N=4096 K=512
    hgemm<MV><<<dim3(16, 4, Bb), 256, GEMM_SMEM>>>(bwv, ht, vv, Cc, Cc, Nn, Cc,
                                                   bv, nullptr, 0, NC_, CN_, 0);
    // s[i][j] = q[i][:] . k[j][:]                  M=4096 N=4096 K=512
    hgemm<MS><<<dim3(16, 32, Bb), 256, GEMM_SMEM>>>(qt, kt, sc, Cc, Cc, Nn, Cc,
                                                    nullptr, nullptr, NC_, NC_, NN_, 0);
    softmax_row_kernel<<<Bb * Nn, 256>>>(sc);
    // o[q][c] = p[q][:] . v[c][:]                  M=4096 N=512 K=4096
    hgemm<MA><<<dim3(2, 32, Bb), 256, GEMM_SMEM>>>(sc, vv, ot, Nn, Nn, Cc, Nn,
                                                   nullptr, nullptr, NN_, CN_, NC_, 0);
    // out[c][n] = Wp[c][:] @ o[n][:] + bp[c] + x   M=512 N=4096 K=512
    hgemm<MP><<<dim3(16, 4, Bb), 256, GEMM_SMEM>>>(bwp, ot, out, Cc, Cc, Nn, Cc,
                                                   bp, x, 0, NC_, CN_, CN_);
}

// round 9
// speedup vs baseline: 1.0092x; 1.0092x over previous
#include <cuda_runtime.h>
#include <cuda_bf16.h>
#include <stdint.h>
#include <math.h>

#define Cc   512
#define Gg   32
#define CPG  16
#define Nn   4096
#define Bb   2
#define EPSf 1e-6f
#define SCALEf 0.04419417382415922f   // 512^-0.5

// ---------------- device scratch (static; no runtime alloc) ----------------
__device__ __nv_bfloat16 g_ht[(size_t)Bb * Nn * Cc];   // h  [b][n][c]
__device__ __nv_bfloat16 g_qt[(size_t)Bb * Nn * Cc];   // q  [b][n][d] (pre-scaled)
__device__ __nv_bfloat16 g_kt[(size_t)Bb * Nn * Cc];   // k  [b][n][d]
__device__ __nv_bfloat16 g_vv[(size_t)Bb * Cc * Nn];   // v  [b][c][n]
__device__ __nv_bfloat16 g_ot[(size_t)Bb * Nn * Cc];   // o  [b][n][c]
__device__ __nv_bfloat16 g_s [(size_t)Bb * Nn * Nn];   // scores / probs [b][i][j]
__device__ __nv_bfloat16 g_wq[Cc * Cc], g_wk[Cc * Cc], g_wv[Cc * Cc], g_wp[Cc * Cc];
__device__ float g_stats[Bb * Gg * 2];

// ---------------- helpers ----------------------------------------------------
__device__ __forceinline__ uint32_t s2u(const void* p) {
    return (uint32_t)__cvta_generic_to_shared((void*)p);
}
__device__ __forceinline__ void cp16(uint32_t saddr, const void* gaddr) {
    asm volatile("cp.async.cg.shared.global [%0], [%1], 16;" :: "r"(saddr), "l"(gaddr));
}
__device__ __forceinline__ void cp_commit() {
    asm volatile("cp.async.commit_group;" ::: "memory");
}
template <int N>
__device__ __forceinline__ void cp_wait() {
    asm volatile("cp.async.wait_group %0;" :: "n"(N) : "memory");
}
__device__ __forceinline__ void ldm4(uint32_t& r0, uint32_t& r1, uint32_t& r2, uint32_t& r3,
                                     uint32_t addr) {
    asm volatile("ldmatrix.sync.aligned.m8n8.x4.shared.b16 {%0,%1,%2,%3}, [%4];"
                 : "=r"(r0), "=r"(r1), "=r"(r2), "=r"(r3) : "r"(addr));
}
__device__ __forceinline__ void mma16816(float* d, const uint32_t* a, const uint32_t* b) {
    asm volatile("mma.sync.aligned.m16n8k16.row.col.f32.bf16.bf16.f32 "
                 "{%0,%1,%2,%3}, {%4,%5,%6,%7}, {%8,%9}, {%0,%1,%2,%3};"
                 : "+f"(d[0]), "+f"(d[1]), "+f"(d[2]), "+f"(d[3])
                 : "r"(a[0]), "r"(a[1]), "r"(a[2]), "r"(a[3]), "r"(b[0]), "r"(b[1]));
}
// SW128 swizzle for 128B rows: element (row, 16B-chunk c in 0..7)
__device__ __forceinline__ uint32_t smoff(int row, int c) {
    return (uint32_t)(row * 128 + ((c ^ (row & 7)) << 4));
}
__device__ __forceinline__ float fexp(float x) {
    x = fmaxf(x, -87.f);
    float z  = x * 1.4426950408889634f;
    float zi = rintf(z);
    float zf = z - zi;
    float r = 1.33978439e-3f;
    r = fmaf(r, zf, 9.67580429e-3f);
    r = fmaf(r, zf, 5.55041087e-2f);
    r = fmaf(r, zf, 2.40226507e-1f);
    r = fmaf(r, zf, 6.93147182e-1f);
    r = fmaf(r, zf, 1.0f);
    return r * __int_as_float(((int)zi + 127) << 23);
}

// ---------------- weight fp32 -> bf16 ---------------------------------------
__global__ void conv_w_kernel(const float* __restrict__ a, const float* __restrict__ b,
                              const float* __restrict__ c, const float* __restrict__ d,
                              __nv_bfloat16* oa, __nv_bfloat16* ob,
                              __nv_bfloat16* oc, __nv_bfloat16* od) {
    int i = blockIdx.x * blockDim.x + threadIdx.x;
    const float4* src[4] = {(const float4*)a, (const float4*)b, (const float4*)c, (const float4*)d};
    __nv_bfloat162* dst[4] = {(__nv_bfloat162*)oa, (__nv_bfloat162*)ob,
                              (__nv_bfloat162*)oc, (__nv_bfloat162*)od};
    #pragma unroll
    for (int m = 0; m < 4; m++) {
        float4 v = src[m][i];
        dst[m][i * 2 + 0] = __nv_bfloat162(__float2bfloat16(v.x), __float2bfloat16(v.y));
        dst[m][i * 2 + 1] = __nv_bfloat162(__float2bfloat16(v.z), __float2bfloat16(v.w));
    }
}

// ---------------- GroupNorm stats -------------------------------------------
__global__ void gn_stats_kernel(const float* __restrict__ x, float* __restrict__ stats) {
    const int bg = blockIdx.x;
    const size_t base = (size_t)bg * CPG * Nn;
    const int n_el = CPG * Nn;
    float s = 0.f, ss = 0.f;
    for (int i = threadIdx.x; i < n_el; i += blockDim.x) {
        float v = x[base + i];
        s += v; ss += v * v;
    }
    __shared__ float red[16];
    #pragma unroll
    for (int o = 16; o; o >>= 1) {
        s  += __shfl_down_sync(0xffffffffu, s,  o);
        ss += __shfl_down_sync(0xffffffffu, ss, o);
    }
    const int wid = threadIdx.x >> 5, lane = threadIdx.x & 31;
    if (lane == 0) { red[wid] = s; red[8 + wid] = ss; }
    __syncthreads();
    if (threadIdx.x == 0) {
        float ts = 0.f, tss = 0.f;
        #pragma unroll
        for (int i = 0; i < 8; i++) { ts += red[i]; tss += red[8 + i]; }
        float mu = ts / (float)n_el;
        float var = tss / (float)n_el - mu * mu;
        stats[bg * 2 + 0] = mu;
        stats[bg * 2 + 1] = rsqrtf(var + EPSf);
    }
}

// ---------------- normalize + transpose x[b][c][n] -> h[b][n][c] bf16 -------
__global__ void gn_norm_t_kernel(const float* __restrict__ x,
                                 const float* __restrict__ w, const float* __restrict__ b,
                                 const float* __restrict__ stats,
                                 __nv_bfloat16* __restrict__ ht) {
    __shared__ float tile[64][65];
    const int n0 = blockIdx.x * 64, c0 = blockIdx.y * 64, bz = blockIdx.z;
    const int tid = threadIdx.x;
    const float* xb = x + (size_t)bz * Cc * Nn;
    #pragma unroll
    for (int i = 0; i < 4; i++) {
        int vi = tid + i * 256;
        int r = vi >> 4, seg = (vi & 15) * 4;
        float4 v = *(const float4*)&xb[(size_t)(c0 + r) * Nn + n0 + seg];
        tile[r][seg + 0] = v.x; tile[r][seg + 1] = v.y;
        tile[r][seg + 2] = v.z; tile[r][seg + 3] = v.w;
    }
    __syncthreads();
    const int nr = tid >> 2, cs = (tid & 3) * 16;
    __nv_bfloat16* hrow = ht + ((size_t)bz * Nn + n0 + nr) * Cc + c0;
    #pragma unroll
    for (int c = 0; c < 16; c++) {
        int cg = cs + c, ch = c0 + cg;
        int sidx = (bz * Gg + (ch >> 4)) * 2;
        float mu = stats[sidx], inv = stats[sidx + 1];
        hrow[cg] = __float2bfloat16((tile[cg][nr] - mu) * inv * w[ch] + b[ch]);
    }
}

// ---------------- bf16 HMMA GEMM: C[M][N] = A[M][K] @ B[N][K]^T --------------
// Tile 128(M) x 256(N) x 64(K), 512 threads (16 warps, 4x4), warp tile 32x64.
// 3-stage cp.async pipeline, ONE barrier per 64-wide k-tile.
enum { MQ = 0, MK = 1, MV = 2, MS = 3, MA = 4, MP = 5 };
#define BKg 64
#define STAGES 3
#define A_BYTES 16384                  // 128 x 64 bf16
#define B_BYTES 32768                  // 256 x 64 bf16
#define STG_BYTES (A_BYTES + B_BYTES)  // 48 KB
#define GEMM_SMEM (STAGES * STG_BYTES) // 144 KB

template <int MODE>
__global__ __launch_bounds__(512, 1)
void hgemm(const __nv_bfloat16* __restrict__ A, const __nv_bfloat16* __restrict__ B,
           void* __restrict__ OutP, int lda, int ldb, int Nd, int K,
           const float* __restrict__ bias, const float* __restrict__ resid,
           long long sA, long long sB, long long sO, long long sR) {
    extern __shared__ char smem[];
    const uint32_t sbase = s2u(smem);
    const int tid = threadIdx.x, lane = tid & 31, warp = tid >> 5;
    const int wmB = (warp >> 2) * 32, wnB = (warp & 3) * 64;   // 4x4 warp grid
    const int m0 = blockIdx.y * 128, n0 = blockIdx.x * 256;
    const int bz = blockIdx.z;

    // cp.async addressing: thread covers rows {rr, rr+64} of A and {rr+64i} of B.
    // smoff(row+64, c) == smoff(row, c) + 8192, so one base swizzle offset suffices.
    const int rr = tid >> 3, cch = tid & 7;
    const uint32_t sof = smoff(rr, cch);
    const __nv_bfloat16* pA = A + (size_t)bz * sA + (size_t)(m0 + rr) * lda + cch * 8;
    const __nv_bfloat16* pB = B + (size_t)bz * sB + (size_t)(n0 + rr) * ldb + cch * 8;
    const size_t strA = (size_t)64 * lda, strB = (size_t)64 * ldb;

    const int NT = K / BKg;
    // ---- prologue: prefetch stages 0..STAGES-2
    #pragma unroll
    for (int t = 0; t < STAGES - 1; t++) {
        if (t < NT) {
            uint32_t sa = sbase + t * STG_BYTES;
            const __nv_bfloat16* a_src = pA + t * BKg;
            const __nv_bfloat16* b_src = pB + t * BKg;
            cp16(sa + sof,                    a_src);
            cp16(sa + sof + 8192,             a_src + strA);
            #pragma unroll
            for (int i = 0; i < 4; i++)
                cp16(sa + A_BYTES + sof + 8192 * i, b_src + strB * i);
        }
        cp_commit();
    }

    float acc[2][8][4];
    #pragma unroll
    for (int i = 0; i < 2; i++)
        #pragma unroll
        for (int j = 0; j < 8; j++)
            #pragma unroll
            for (int k = 0; k < 4; k++) acc[i][j][k] = 0.f;

    const int aRow = lane & 15, aC = lane >> 4;
    const int bRow = (lane & 7) + ((lane & 16) >> 1), bC = (lane >> 3) & 1;

    for (int t = 0; t < NT; t++) {
        if (t >= NT - (STAGES - 1)) cp_wait<0>(); else cp_wait<STAGES - 2>();
        __syncthreads();     // stage t ready; all warps done reading the slot
                             // that this iteration's prefetch overwrites
        if (t + STAGES - 1 < NT) {
            int tp = t + STAGES - 1;
            uint32_t sa = sbase + (tp % STAGES) * STG_BYTES;
            const __nv_bfloat16* a_src = pA + tp * BKg;
            const __nv_bfloat16* b_src = pB + tp * BKg;
            cp16(sa + sof,                    a_src);
            cp16(sa + sof + 8192,             a_src + strA);
            #pragma unroll
            for (int i = 0; i < 4; i++)
                cp16(sa + A_BYTES + sof + 8192 * i, b_src + strB * i);
        }
        cp_commit();
        const uint32_t aS = sbase + (t % STAGES) * STG_BYTES;
        const uint32_t bS = aS + A_BYTES;
        #pragma unroll
        for (int kk = 0; kk < 4; kk++) {
            uint32_t af[2][4], bf[8][2];
            #pragma unroll
            for (int mf = 0; mf < 2; mf++)
                ldm4(af[mf][0], af[mf][1], af[mf][2], af[mf][3],
                     aS + smoff(wmB + mf * 16 + aRow, kk * 2 + aC));
            #pragma unroll
            for (int g = 0; g < 4; g++)
                ldm4(bf[2 * g][0], bf[2 * g][1], bf[2 * g + 1][0], bf[2 * g + 1][1],
                     bS + smoff(wnB + g * 16 + bRow, kk * 2 + bC));
            #pragma unroll
            for (int mf = 0; mf < 2; mf++)
                #pragma unroll
                for (int nf = 0; nf < 8; nf++)
                    mma16816(acc[mf][nf], af[mf], bf[nf]);
        }
    }

    // ---- epilogue
    float* Of = (float*)OutP + (size_t)bz * sO;
    __nv_bfloat16* Oh = (__nv_bfloat16*)OutP + (size_t)bz * sO;
    const float* Rz = resid + (size_t)bz * sR;
    #pragma unroll
    for (int mf = 0; mf < 2; mf++) {
        #pragma unroll
        for (int pr = 0; pr < 2; pr++) {
            const int row = m0 + wmB + mf * 16 + (lane >> 2) + pr * 8;
            float rb = 0.f;
            if (MODE == MV || MODE == MP) rb = bias[row];
            #pragma unroll
            for (int nf = 0; nf < 8; nf++) {
                const int col = n0 + wnB + nf * 8 + (lane & 3) * 2;
                float v0 = acc[mf][nf][pr * 2 + 0];
                float v1 = acc[mf][nf][pr * 2 + 1];
                if (MODE == MQ) { v0 = (v0 + bias[col]) * SCALEf; v1 = (v1 + bias[col + 1]) * SCALEf; }
                if (MODE == MK) { v0 += bias[col]; v1 += bias[col + 1]; }
                if (MODE == MV || MODE == MP) { v0 += rb; v1 += rb; }
                const size_t oi = (size_t)row * Nd + col;
                if (MODE == MP) {
                    float2 rrv = *(const float2*)&Rz[oi];
                    *(float2*)&Of[oi] = make_float2(v0 + rrv.x, v1 + rrv.y);
                } else {
                    *(__nv_bfloat162*)&Oh[oi] =
                        __nv_bfloat162(__float2bfloat16(v0), __float2bfloat16(v1));
                }
            }
        }
    }
}

// ---------------- row softmax (in-place, bf16 rows of 4096) -----------------
__global__ void softmax_row_kernel(__nv_bfloat16* __restrict__ s) {
    __nv_bfloat16* p = s + (size_t)blockIdx.x * Nn;
    const int tid = threadIdx.x;
    float v[16];
    uint4 raw[2];
    #pragma unroll
    for (int h = 0; h < 2; h++) {
        raw[h] = *(const uint4*)(p + (tid + h * 256) * 8);
        const __nv_bfloat16* pb = (const __nv_bfloat16*)&raw[h];
        #pragma unroll
        for (int e = 0; e < 8; e++) v[h * 8 + e] = __bfloat162float(pb[e]);
    }
    float mx = -1e30f;
    #pragma unroll
    for (int i = 0; i < 16; i++) mx = fmaxf(mx, v[i]);
    __shared__ float red[8];
    const int wid = tid >> 5, lane = tid & 31;
    #pragma unroll
    for (int o = 16; o; o >>= 1) mx = fmaxf(mx, __shfl_xor_sync(0xffffffffu, mx, o));
    if (lane == 0) red[wid] = mx;
    __syncthreads();
    mx = red[0];
    #pragma unroll
    for (int i = 1; i < 8; i++) mx = fmaxf(mx, red[i]);
    __syncthreads();
    float sum = 0.f;
    #pragma unroll
    for (int i = 0; i < 16; i++) { v[i] = fexp(v[i] - mx); sum += v[i]; }
    #pragma unroll
    for (int o = 16; o; o >>= 1) sum += __shfl_xor_sync(0xffffffffu, sum, o);
    if (lane == 0) red[wid] = sum;
    __syncthreads();
    sum = 0.f;
    #pragma unroll
    for (int i = 0; i < 8; i++) sum += red[i];
    const float inv = 1.f / sum;
    #pragma unroll
    for (int h = 0; h < 2; h++) {
        uint4 outp;
        __nv_bfloat16* ob = (__nv_bfloat16*)&outp;
        #pragma unroll
        for (int e = 0; e < 8; e++) ob[e] = __float2bfloat16(v[h * 8 + e] * inv);
        *(uint4*)(p + (tid + h * 256) * 8) = outp;
    }
}

// ---------------- launch -----------------------------------------------------
extern "C" void kernel_launch(void* const* d_in, const int* in_sizes, int n_in,
                              void* d_out, int out_size) {
    const float* x  = (const float*)d_in[0];
    const float* gw = (const float*)d_in[1];
    const float* gb = (const float*)d_in[2];
    const float* wq = (const float*)d_in[3];
    const float* bq = (const float*)d_in[4];
    const float* wk = (const float*)d_in[5];
    const float* bk = (const float*)d_in[6];
    const float* wv = (const float*)d_in[7];
    const float* bv = (const float*)d_in[8];
    const float* wp = (const float*)d_in[9];
    const float* bp = (const float*)d_in[10];
    float* out = (float*)d_out;

    __nv_bfloat16 *ht, *qt, *kt, *vv, *ot, *sc, *bwq, *bwk, *bwv, *bwp;
    float* stats;
    cudaGetSymbolAddress((void**)&ht, g_ht);
    cudaGetSymbolAddress((void**)&qt, g_qt);
    cudaGetSymbolAddress((void**)&kt, g_kt);
    cudaGetSymbolAddress((void**)&vv, g_vv);
    cudaGetSymbolAddress((void**)&ot, g_ot);
    cudaGetSymbolAddress((void**)&sc, g_s);
    cudaGetSymbolAddress((void**)&bwq, g_wq);
    cudaGetSymbolAddress((void**)&bwk, g_wk);
    cudaGetSymbolAddress((void**)&bwv, g_wv);
    cudaGetSymbolAddress((void**)&bwp, g_wp);
    cudaGetSymbolAddress((void**)&stats, g_stats);

    cudaFuncSetAttribute(hgemm<MQ>, cudaFuncAttributeMaxDynamicSharedMemorySize, GEMM_SMEM);
    cudaFuncSetAttribute(hgemm<MK>, cudaFuncAttributeMaxDynamicSharedMemorySize, GEMM_SMEM);
    cudaFuncSetAttribute(hgemm<MV>, cudaFuncAttributeMaxDynamicSharedMemorySize, GEMM_SMEM);
    cudaFuncSetAttribute(hgemm<MS>, cudaFuncAttributeMaxDynamicSharedMemorySize, GEMM_SMEM);
    cudaFuncSetAttribute(hgemm<MA>, cudaFuncAttributeMaxDynamicSharedMemorySize, GEMM_SMEM);
    cudaFuncSetAttribute(hgemm<MP>, cudaFuncAttributeMaxDynamicSharedMemorySize, GEMM_SMEM);

    const long long NC_ = (long long)Nn * Cc;
    const long long CN_ = (long long)Cc * Nn;
    const long long NN_ = (long long)Nn * Nn;

    conv_w_kernel<<<256, 256>>>(wq, wk, wv, wp, bwq, bwk, bwv, bwp);
    gn_stats_kernel<<<Bb * Gg, 256>>>(x, stats);
    gn_norm_t_kernel<<<dim3(Nn / 64, Cc / 64, Bb), 256>>>(x, gw, gb, stats, ht);

    // q[n][d] = scale*(h[n][:] @ Wq[d][:] + bq)    M=4096 N=512 K=512
    hgemm<MQ><<<dim3(2, 32, Bb), 512, GEMM_SMEM>>>(ht, bwq, qt, Cc, Cc, Cc, Cc,
                                                   bq, nullptr, NC_, 0, NC_, 0);
    hgemm<MK><<<dim3(2, 32, Bb), 512, GEMM_SMEM>>>(ht, bwk, kt, Cc, Cc, Cc, Cc,
                                                   bk, nullptr, NC_, 0, NC_, 0);
    // v[c][n] = Wv[c][:] @ h[n][:] + bv[c]         M=512 N=4096 K=512
    hgemm<MV><<<dim3(16, 4, Bb), 512, GEMM_SMEM>>>(bwv, ht, vv, Cc, Cc, Nn, Cc,
                                                   bv, nullptr, 0, NC_, CN_, 0);
    // s[i][j] = q[i][:] . k[j][:]                  M=4096 N=4096 K=512
    hgemm<MS><<<dim3(16, 32, Bb), 512, GEMM_SMEM>>>(qt, kt, sc, Cc, Cc, Nn, Cc,
                                                    nullptr, nullptr, NC_, NC_, NN_, 0);
    softmax_row_kernel<<<Bb * Nn, 256>>>(sc);
    // o[q][c] = p[q][:] . v[c][:]                  M=4096 N=512 K=4096
    hgemm<MA><<<dim3(2, 32, Bb), 512, GEMM_SMEM>>>(sc, vv, ot, Nn, Nn, Cc, Nn,
                                                   nullptr, nullptr, NN_, CN_, NC_, 0);
    // out[c][n] = Wp[c][:] @ o[n][:] + bp[c] + x   M=512 N=4096 K=512
    hgemm<MP><<<dim3(16, 4, Bb), 512, GEMM_SMEM>>>(bwp, ot, out, Cc, Cc, Nn, Cc,
                                                   bp, x, 0, NC_, CN_, CN_);
}